// round 1
// baseline (speedup 1.0000x reference)
#include <cuda_runtime.h>
#include <math.h>
#include <stdint.h>

// Problem constants
#define T_LEN 2048
#define C_DIM 1024
#define H_NUM 16
#define KVH_NUM 4
#define D_DIM 64
#define KV_DIM 256
#define ATTN_SCALE 0.125f   // 1/sqrt(64)
#define NEG_BIG -1e30f

// Scratch (device globals: allocation-free)
__device__ float g_q[T_LEN * C_DIM];     // q after proj -> rmsnorm -> rope (in place)
__device__ float g_k[T_LEN * KV_DIM];    // k after proj -> rmsnorm -> rope (in place)
__device__ float g_v[T_LEN * KV_DIM];    // v = x @ Wv^T
__device__ float g_y[T_LEN * C_DIM];     // attention output [T, H*D]
__device__ float g_logf[H_NUM * T_LEN];  // per-head log f_t
__device__ float g_c[H_NUM * T_LEN];     // per-head cumsum of log f_t

// ---------------------------------------------------------------------------
// GEMM: O[M,N] = A[M,K] @ W[N,K]^T   (both operands K-contiguous, row-major)
// 64x64 block tile, BK=32, 256 threads, 4x4 per-thread register tile.
// Tiles stored transposed in smem so the inner loop uses float4 LDS.
// ---------------------------------------------------------------------------
__global__ void gemm_nt_kernel(const float* __restrict__ A,
                               const float* __restrict__ W,
                               float* __restrict__ O, int K, int N) {
    __shared__ float As[32][64];
    __shared__ float Ws[32][64];
    const int m0 = blockIdx.y << 6;
    const int n0 = blockIdx.x << 6;
    const int tx = threadIdx.x & 15;
    const int ty = threadIdx.x >> 4;

    float acc[4][4];
#pragma unroll
    for (int i = 0; i < 4; i++)
#pragma unroll
        for (int j = 0; j < 4; j++) acc[i][j] = 0.f;

    for (int k0 = 0; k0 < K; k0 += 32) {
#pragma unroll
        for (int l = threadIdx.x; l < 512; l += 256) {
            int r = l >> 3;
            int c4 = (l & 7) << 2;
            float4 av = *(const float4*)(A + (size_t)(m0 + r) * K + k0 + c4);
            As[c4 + 0][r] = av.x; As[c4 + 1][r] = av.y;
            As[c4 + 2][r] = av.z; As[c4 + 3][r] = av.w;
            float4 wv = *(const float4*)(W + (size_t)(n0 + r) * K + k0 + c4);
            Ws[c4 + 0][r] = wv.x; Ws[c4 + 1][r] = wv.y;
            Ws[c4 + 2][r] = wv.z; Ws[c4 + 3][r] = wv.w;
        }
        __syncthreads();
#pragma unroll
        for (int kk = 0; kk < 32; kk++) {
            float4 a = *(const float4*)&As[kk][ty << 2];
            float4 b = *(const float4*)&Ws[kk][tx << 2];
            float av4[4] = {a.x, a.y, a.z, a.w};
            float bv4[4] = {b.x, b.y, b.z, b.w};
#pragma unroll
            for (int i = 0; i < 4; i++)
#pragma unroll
                for (int j = 0; j < 4; j++) acc[i][j] += av4[i] * bv4[j];
        }
        __syncthreads();
    }
#pragma unroll
    for (int i = 0; i < 4; i++)
#pragma unroll
        for (int j = 0; j < 4; j++)
            O[(size_t)(m0 + (ty << 2) + i) * N + n0 + (tx << 2) + j] = acc[i][j];
}

// ---------------------------------------------------------------------------
// RMSNorm (over full row) + RoPE (per 64-wide head), in place, for q and k.
// One block per token row, 256 threads.
// ---------------------------------------------------------------------------
__global__ void normrope_kernel(float* __restrict__ q, float* __restrict__ k,
                                const float* __restrict__ qw,
                                const float* __restrict__ kw) {
    const int t = blockIdx.x;
    const int tid = threadIdx.x;
    __shared__ float buf[C_DIM];
    __shared__ float red[8];
    __shared__ float s_inv;

    // ---- Q: rmsnorm over C=1024 ----
    float ss = 0.f;
    for (int c = tid; c < C_DIM; c += 256) {
        float vv = q[(size_t)t * C_DIM + c];
        buf[c] = vv;
        ss += vv * vv;
    }
#pragma unroll
    for (int o = 16; o; o >>= 1) ss += __shfl_xor_sync(0xffffffffu, ss, o);
    if ((tid & 31) == 0) red[tid >> 5] = ss;
    __syncthreads();
    if (tid == 0) {
        float tot = 0.f;
#pragma unroll
        for (int w = 0; w < 8; w++) tot += red[w];
        s_inv = rsqrtf(tot / (float)C_DIM + 1e-6f);
    }
    __syncthreads();
    float inv = s_inv;
    for (int c = tid; c < C_DIM; c += 256) {
        int d = c & 63;
        float xn = buf[c] * inv * qw[c];
        float other;
        int f;
        if (d < 32) { other = -buf[c + 32] * inv * qw[c + 32]; f = d; }
        else        { other =  buf[c - 32] * inv * qw[c - 32]; f = d - 32; }
        float th = (float)t * powf(10000.0f, -(float)(2 * f) / 64.0f);
        q[(size_t)t * C_DIM + c] = xn * cosf(th) + other * sinf(th);
    }
    __syncthreads();

    // ---- K: rmsnorm over KV=256 ----
    float ss2 = 0.f;
    if (tid < KV_DIM) {
        float vv = k[(size_t)t * KV_DIM + tid];
        buf[tid] = vv;
        ss2 = vv * vv;
    }
#pragma unroll
    for (int o = 16; o; o >>= 1) ss2 += __shfl_xor_sync(0xffffffffu, ss2, o);
    if ((tid & 31) == 0) red[tid >> 5] = ss2;
    __syncthreads();
    if (tid == 0) {
        float tot = 0.f;
#pragma unroll
        for (int w = 0; w < 8; w++) tot += red[w];
        s_inv = rsqrtf(tot / (float)KV_DIM + 1e-6f);
    }
    __syncthreads();
    inv = s_inv;
    if (tid < KV_DIM) {
        int c = tid;
        int d = c & 63;
        float xn = buf[c] * inv * kw[c];
        float other;
        int f;
        if (d < 32) { other = -buf[c + 32] * inv * kw[c + 32]; f = d; }
        else        { other =  buf[c - 32] * inv * kw[c - 32]; f = d - 32; }
        float th = (float)t * powf(10000.0f, -(float)(2 * f) / 64.0f);
        k[(size_t)t * KV_DIM + c] = xn * cosf(th) + other * sinf(th);
    }
}

// ---------------------------------------------------------------------------
// Forgetting gate: per (t, h) compute
//   lam   = elu(x_t . wl[:,h]) + 1
//   logit = (x_t . fg[h,:] + fb[h]) * lam
//   logf  = log_sigmoid(logit) / (lam + 1e-3)
// One block per token, 128 threads = 16 heads x 8 lanes.
// ---------------------------------------------------------------------------
__global__ void gate_kernel(const float* __restrict__ x,
                            const float* __restrict__ wl,   // [C, H]
                            const float* __restrict__ fg,   // [H, C]
                            const float* __restrict__ fb,   // [H]
                            float* __restrict__ logf_out) { // [H, T]
    const int t = blockIdx.x;
    const int tid = threadIdx.x;
    __shared__ float xs[C_DIM];
    for (int c = tid; c < C_DIM; c += 128) xs[c] = x[(size_t)t * C_DIM + c];
    __syncthreads();

    const int head = tid >> 3;
    const int l8 = tid & 7;
    float z1 = 0.f, z2 = 0.f;
    for (int c = l8; c < C_DIM; c += 8) {
        float xv = xs[c];
        z1 += xv * wl[(size_t)c * H_NUM + head];
        z2 += xv * fg[(size_t)head * C_DIM + c];
    }
#pragma unroll
    for (int o = 4; o; o >>= 1) {
        z1 += __shfl_xor_sync(0xffffffffu, z1, o);
        z2 += __shfl_xor_sync(0xffffffffu, z2, o);
    }
    if (l8 == 0) {
        float lam = (z1 > 0.f ? z1 : expf(z1) - 1.f) + 1.f;
        float logit = (z2 + fb[head]) * lam;
        float ls = (logit >= 0.f) ? -log1pf(expf(-logit))
                                  : (logit - log1pf(expf(logit)));
        logf_out[(size_t)head * T_LEN + t] = ls / (lam + 1e-3f);
    }
}

// ---------------------------------------------------------------------------
// Inclusive cumsum per head: one warp per head, 64 elements per lane.
// ---------------------------------------------------------------------------
__global__ void scan_kernel(const float* __restrict__ lf, float* __restrict__ c) {
    const int h = blockIdx.x;
    const int lane = threadIdx.x;
    const float* src = lf + (size_t)h * T_LEN;
    float* dst = c + (size_t)h * T_LEN;
    const int base = lane * 64;
    float s = 0.f;
#pragma unroll 8
    for (int i = 0; i < 64; i++) s += src[base + i];
    float incl = s;
#pragma unroll
    for (int o = 1; o < 32; o <<= 1) {
        float vv = __shfl_up_sync(0xffffffffu, incl, o);
        if (lane >= o) incl += vv;
    }
    float run = incl - s;  // exclusive prefix of this chunk
#pragma unroll 8
    for (int i = 0; i < 64; i++) {
        run += src[base + i];
        dst[base + i] = run;
    }
}

// ---------------------------------------------------------------------------
// Flash attention with forgetting-gate bias (c_i - c_j), causal, GQA.
// Block: (query tile of 16 rows, head). 128 threads = 16 rows x 8 sub-lanes.
// Key tiles of 32. Online softmax. Smem padded to stride 65 (bank spread).
// ---------------------------------------------------------------------------
__global__ void attn_kernel(const float* __restrict__ q,
                            const float* __restrict__ k,
                            const float* __restrict__ v,
                            const float* __restrict__ cg,
                            float* __restrict__ y) {
    __shared__ float qs[16][65];
    __shared__ float ks[32][65];
    __shared__ float vs[32][65];
    __shared__ float ps[16][32];

    const int h = blockIdx.y;
    const int kvh = h >> 2;             // repeat_interleave: head h -> kv head h/4
    const int i0 = blockIdx.x << 4;
    const int tid = threadIdx.x;
    const int row = tid >> 3;
    const int sub = tid & 7;
    const int i = i0 + row;
    const int jb = sub << 2;
    const int db = sub << 3;

    for (int l = tid; l < 16 * 64; l += 128) {
        int r = l >> 6, d = l & 63;
        qs[r][d] = q[(size_t)(i0 + r) * C_DIM + h * 64 + d];
    }
    const float ci = cg[(size_t)h * T_LEN + i];

    float m = NEG_BIG, lsum = 0.f;
    float acc[8];
#pragma unroll
    for (int e = 0; e < 8; e++) acc[e] = 0.f;

    const int ntiles = ((i0 + 15) >> 5) + 1;
    for (int tk = 0; tk < ntiles; tk++) {
        const int j0 = tk << 5;
        __syncthreads();
        for (int l = tid; l < 32 * 64; l += 128) {
            int r = l >> 6, d = l & 63;
            ks[r][d] = k[(size_t)(j0 + r) * KV_DIM + kvh * 64 + d];
            vs[r][d] = v[(size_t)(j0 + r) * KV_DIM + kvh * 64 + d];
        }
        __syncthreads();

        float s0 = 0.f, s1 = 0.f, s2 = 0.f, s3 = 0.f;
#pragma unroll
        for (int d = 0; d < 64; d++) {
            float qv = qs[row][d];
            s0 += qv * ks[jb + 0][d];
            s1 += qv * ks[jb + 1][d];
            s2 += qv * ks[jb + 2][d];
            s3 += qv * ks[jb + 3][d];
        }
        float s[4] = {s0, s1, s2, s3};
        float mt = NEG_BIG;
#pragma unroll
        for (int jj = 0; jj < 4; jj++) {
            int j = j0 + jb + jj;
            if (j <= i)
                s[jj] = s[jj] * ATTN_SCALE + ci - cg[(size_t)h * T_LEN + j];
            else
                s[jj] = NEG_BIG;
            mt = fmaxf(mt, s[jj]);
        }
#pragma unroll
        for (int o = 4; o; o >>= 1) mt = fmaxf(mt, __shfl_xor_sync(0xffffffffu, mt, o));
        const float mnew = fmaxf(m, mt);
        const float alpha = expf(m - mnew);   // expf(-huge)=0 on first tile
        float psum = 0.f;
#pragma unroll
        for (int jj = 0; jj < 4; jj++) {
            float p = expf(s[jj] - mnew);
            ps[row][jb + jj] = p;
            psum += p;
        }
#pragma unroll
        for (int o = 4; o; o >>= 1) psum += __shfl_xor_sync(0xffffffffu, psum, o);
        lsum = lsum * alpha + psum;
        m = mnew;
#pragma unroll
        for (int e = 0; e < 8; e++) acc[e] *= alpha;
        __syncwarp();
#pragma unroll 8
        for (int j = 0; j < 32; j++) {
            float p = ps[row][j];
#pragma unroll
            for (int e = 0; e < 8; e++) acc[e] += p * vs[j][db + e];
        }
    }

    const float invl = 1.f / lsum;
#pragma unroll
    for (int e = 0; e < 8; e++)
        y[(size_t)i * C_DIM + h * 64 + db + e] = acc[e] * invl;
}

// ---------------------------------------------------------------------------
// kernel_launch
// Inputs (metadata order): x, Wq, Wk, Wv, Wo, q_norm_w, k_norm_w,
//                          fgate_w, fgate_b, weight_lambda
// ---------------------------------------------------------------------------
extern "C" void kernel_launch(void* const* d_in, const int* in_sizes, int n_in,
                              void* d_out, int out_size) {
    const float* x  = (const float*)d_in[0];
    const float* Wq = (const float*)d_in[1];
    const float* Wk = (const float*)d_in[2];
    const float* Wv = (const float*)d_in[3];
    const float* Wo = (const float*)d_in[4];
    const float* qw = (const float*)d_in[5];
    const float* kw = (const float*)d_in[6];
    const float* fg = (const float*)d_in[7];
    const float* fb = (const float*)d_in[8];
    const float* wl = (const float*)d_in[9];
    float* out = (float*)d_out;

    float *qp, *kp, *vp, *yp, *lfp, *cp;
    cudaGetSymbolAddress((void**)&qp, g_q);
    cudaGetSymbolAddress((void**)&kp, g_k);
    cudaGetSymbolAddress((void**)&vp, g_v);
    cudaGetSymbolAddress((void**)&yp, g_y);
    cudaGetSymbolAddress((void**)&lfp, g_logf);
    cudaGetSymbolAddress((void**)&cp, g_c);

    // Projections
    gemm_nt_kernel<<<dim3(C_DIM / 64, T_LEN / 64), 256>>>(x, Wq, qp, C_DIM, C_DIM);
    gemm_nt_kernel<<<dim3(KV_DIM / 64, T_LEN / 64), 256>>>(x, Wk, kp, C_DIM, KV_DIM);
    gemm_nt_kernel<<<dim3(KV_DIM / 64, T_LEN / 64), 256>>>(x, Wv, vp, C_DIM, KV_DIM);

    // RMSNorm + RoPE (in place on q, k)
    normrope_kernel<<<T_LEN, 256>>>(qp, kp, qw, kw);

    // Forgetting gate + per-head cumsum
    gate_kernel<<<T_LEN, 128>>>(x, wl, fg, fb, lfp);
    scan_kernel<<<H_NUM, 32>>>(lfp, cp);

    // Attention
    attn_kernel<<<dim3(T_LEN / 16, H_NUM), 128>>>(qp, kp, vp, cp, yp);

    // Output projection
    gemm_nt_kernel<<<dim3(C_DIM / 64, T_LEN / 64), 256>>>(yp, Wo, out, C_DIM, C_DIM);
}

// round 2
// speedup vs baseline: 4.7758x; 4.7758x over previous
#include <cuda_runtime.h>
#include <math.h>
#include <stdint.h>

// Problem constants
#define T_LEN 2048
#define C_DIM 1024
#define H_NUM 16
#define KVH_NUM 4
#define D_DIM 64
#define KV_DIM 256
#define ATTN_SCALE 0.125f   // 1/sqrt(64)
#define NEG_BIG -1e30f

// Scratch (device globals: allocation-free)
__device__ float g_q[T_LEN * C_DIM];
__device__ float g_k[T_LEN * KV_DIM];
__device__ float g_v[T_LEN * KV_DIM];
__device__ float g_y[T_LEN * C_DIM];
__device__ float g_logf[H_NUM * T_LEN];
__device__ float g_c[H_NUM * T_LEN];

// ---------------------------------------------------------------------------
// tf32 helpers
// ---------------------------------------------------------------------------
__device__ __forceinline__ uint32_t tf32r(float x) {
    uint32_t u;
    asm("cvt.rna.tf32.f32 %0, %1;" : "=r"(u) : "f"(x));
    return u;
}
__device__ __forceinline__ float4 tf32r4(float4 v) {
    return make_float4(__uint_as_float(tf32r(v.x)), __uint_as_float(tf32r(v.y)),
                       __uint_as_float(tf32r(v.z)), __uint_as_float(tf32r(v.w)));
}
// D += A(16x8 tf32, row) * B(8x8 tf32, col), fp32 accum
__device__ __forceinline__ void mma_tf32(float* c, const uint32_t* a,
                                         uint32_t b0, uint32_t b1) {
    asm volatile(
        "mma.sync.aligned.m16n8k8.row.col.f32.tf32.tf32.f32 "
        "{%0,%1,%2,%3}, {%4,%5,%6,%7}, {%8,%9}, {%0,%1,%2,%3};"
        : "+f"(c[0]), "+f"(c[1]), "+f"(c[2]), "+f"(c[3])
        : "r"(a[0]), "r"(a[1]), "r"(a[2]), "r"(a[3]), "r"(b0), "r"(b1));
}

// ---------------------------------------------------------------------------
// GEMM: O[M,N] = A[M,K] @ W[N,K]^T   via tf32 mma.sync
// Block tile 128x64, 256 threads (8 warps), warp tile 32x32.
// Smem padded to stride 36 -> conflict-free fragment loads.
// ---------------------------------------------------------------------------
#define GP 36
__global__ __launch_bounds__(256, 2)
void gemm_tf32_kernel(const float* __restrict__ A, const float* __restrict__ W,
                      float* __restrict__ O, int K, int N) {
    __shared__ float As[128][GP];
    __shared__ float Ws[64][GP];
    const int m0 = blockIdx.y << 7;
    const int n0 = blockIdx.x << 6;
    const int tid = threadIdx.x;
    const int wid = tid >> 5, lane = tid & 31;
    const int grp = lane >> 2, tg = lane & 3;
    const int wm = (wid & 3) << 5, wn = (wid >> 2) << 5;

    float acc[2][4][4] = {};

    for (int k0 = 0; k0 < K; k0 += 32) {
        __syncthreads();
#pragma unroll
        for (int t = 0; t < 4; t++) {
            int idx = tid + (t << 8);
            int r = idx >> 3, c4 = (idx & 7) << 2;
            float4 gv = *(const float4*)(A + (size_t)(m0 + r) * K + k0 + c4);
            *(float4*)&As[r][c4] = tf32r4(gv);
        }
#pragma unroll
        for (int t = 0; t < 2; t++) {
            int idx = tid + (t << 8);
            int r = idx >> 3, c4 = (idx & 7) << 2;
            float4 gv = *(const float4*)(W + (size_t)(n0 + r) * K + k0 + c4);
            *(float4*)&Ws[r][c4] = tf32r4(gv);
        }
        __syncthreads();
#pragma unroll
        for (int kb = 0; kb < 32; kb += 8) {
            uint32_t afr[2][4];
#pragma unroll
            for (int mt = 0; mt < 2; mt++) {
                int mr = wm + (mt << 4);
                afr[mt][0] = __float_as_uint(As[mr + grp][kb + tg]);
                afr[mt][1] = __float_as_uint(As[mr + 8 + grp][kb + tg]);
                afr[mt][2] = __float_as_uint(As[mr + grp][kb + tg + 4]);
                afr[mt][3] = __float_as_uint(As[mr + 8 + grp][kb + tg + 4]);
            }
#pragma unroll
            for (int nt = 0; nt < 4; nt++) {
                int nc = wn + (nt << 3);
                uint32_t b0 = __float_as_uint(Ws[nc + grp][kb + tg]);
                uint32_t b1 = __float_as_uint(Ws[nc + grp][kb + tg + 4]);
                mma_tf32(acc[0][nt], afr[0], b0, b1);
                mma_tf32(acc[1][nt], afr[1], b0, b1);
            }
        }
    }
#pragma unroll
    for (int mt = 0; mt < 2; mt++)
#pragma unroll
        for (int nt = 0; nt < 4; nt++) {
            int row = m0 + wm + (mt << 4) + grp;
            int col = n0 + wn + (nt << 3) + (tg << 1);
            *(float2*)&O[(size_t)row * N + col] =
                make_float2(acc[mt][nt][0], acc[mt][nt][1]);
            *(float2*)&O[(size_t)(row + 8) * N + col] =
                make_float2(acc[mt][nt][2], acc[mt][nt][3]);
        }
}

// ---------------------------------------------------------------------------
// RMSNorm + RoPE, in place, q and k (one block per token)
// ---------------------------------------------------------------------------
__global__ void normrope_kernel(float* __restrict__ q, float* __restrict__ k,
                                const float* __restrict__ qw,
                                const float* __restrict__ kw) {
    const int t = blockIdx.x;
    const int tid = threadIdx.x;
    __shared__ float buf[C_DIM];
    __shared__ float red[8];
    __shared__ float s_inv;

    float ss = 0.f;
    for (int c = tid; c < C_DIM; c += 256) {
        float vv = q[(size_t)t * C_DIM + c];
        buf[c] = vv;
        ss += vv * vv;
    }
#pragma unroll
    for (int o = 16; o; o >>= 1) ss += __shfl_xor_sync(0xffffffffu, ss, o);
    if ((tid & 31) == 0) red[tid >> 5] = ss;
    __syncthreads();
    if (tid == 0) {
        float tot = 0.f;
#pragma unroll
        for (int w = 0; w < 8; w++) tot += red[w];
        s_inv = rsqrtf(tot / (float)C_DIM + 1e-6f);
    }
    __syncthreads();
    float inv = s_inv;
    for (int c = tid; c < C_DIM; c += 256) {
        int d = c & 63;
        float xn = buf[c] * inv * qw[c];
        float other;
        int f;
        if (d < 32) { other = -buf[c + 32] * inv * qw[c + 32]; f = d; }
        else        { other =  buf[c - 32] * inv * qw[c - 32]; f = d - 32; }
        float th = (float)t * powf(10000.0f, -(float)(2 * f) / 64.0f);
        q[(size_t)t * C_DIM + c] = xn * cosf(th) + other * sinf(th);
    }
    __syncthreads();

    float ss2 = 0.f;
    if (tid < KV_DIM) {
        float vv = k[(size_t)t * KV_DIM + tid];
        buf[tid] = vv;
        ss2 = vv * vv;
    }
#pragma unroll
    for (int o = 16; o; o >>= 1) ss2 += __shfl_xor_sync(0xffffffffu, ss2, o);
    if ((tid & 31) == 0) red[tid >> 5] = ss2;
    __syncthreads();
    if (tid == 0) {
        float tot = 0.f;
#pragma unroll
        for (int w = 0; w < 8; w++) tot += red[w];
        s_inv = rsqrtf(tot / (float)KV_DIM + 1e-6f);
    }
    __syncthreads();
    inv = s_inv;
    if (tid < KV_DIM) {
        int c = tid;
        int d = c & 63;
        float xn = buf[c] * inv * kw[c];
        float other;
        int f;
        if (d < 32) { other = -buf[c + 32] * inv * kw[c + 32]; f = d; }
        else        { other =  buf[c - 32] * inv * kw[c - 32]; f = d - 32; }
        float th = (float)t * powf(10000.0f, -(float)(2 * f) / 64.0f);
        k[(size_t)t * KV_DIM + c] = xn * cosf(th) + other * sinf(th);
    }
}

// ---------------------------------------------------------------------------
// Forgetting gate
// ---------------------------------------------------------------------------
__global__ void gate_kernel(const float* __restrict__ x,
                            const float* __restrict__ wl,
                            const float* __restrict__ fg,
                            const float* __restrict__ fb,
                            float* __restrict__ logf_out) {
    const int t = blockIdx.x;
    const int tid = threadIdx.x;
    __shared__ float xs[C_DIM];
    for (int c = tid; c < C_DIM; c += 128) xs[c] = x[(size_t)t * C_DIM + c];
    __syncthreads();

    const int head = tid >> 3;
    const int l8 = tid & 7;
    float z1 = 0.f, z2 = 0.f;
    for (int c = l8; c < C_DIM; c += 8) {
        float xv = xs[c];
        z1 += xv * wl[(size_t)c * H_NUM + head];
        z2 += xv * fg[(size_t)head * C_DIM + c];
    }
#pragma unroll
    for (int o = 4; o; o >>= 1) {
        z1 += __shfl_xor_sync(0xffffffffu, z1, o);
        z2 += __shfl_xor_sync(0xffffffffu, z2, o);
    }
    if (l8 == 0) {
        float lam = (z1 > 0.f ? z1 : expf(z1) - 1.f) + 1.f;
        float logit = (z2 + fb[head]) * lam;
        float ls = (logit >= 0.f) ? -log1pf(expf(-logit))
                                  : (logit - log1pf(expf(logit)));
        logf_out[(size_t)head * T_LEN + t] = ls / (lam + 1e-3f);
    }
}

// ---------------------------------------------------------------------------
// Per-head inclusive cumsum
// ---------------------------------------------------------------------------
__global__ void scan_kernel(const float* __restrict__ lf, float* __restrict__ c) {
    const int h = blockIdx.x;
    const int lane = threadIdx.x;
    const float* src = lf + (size_t)h * T_LEN;
    float* dst = c + (size_t)h * T_LEN;
    const int base = lane * 64;
    float s = 0.f;
#pragma unroll 8
    for (int i = 0; i < 64; i++) s += src[base + i];
    float incl = s;
#pragma unroll
    for (int o = 1; o < 32; o <<= 1) {
        float vv = __shfl_up_sync(0xffffffffu, incl, o);
        if (lane >= o) incl += vv;
    }
    float run = incl - s;
#pragma unroll 8
    for (int i = 0; i < 64; i++) {
        run += src[base + i];
        dst[base + i] = run;
    }
}

// ---------------------------------------------------------------------------
// Flash attention via tf32 mma.sync. 64 queries x 64 keys per tile,
// 4 warps x 16 rows. S and O live in mma accumulators; P routed through
// smem reusing the K buffer (union). Stride-68 padding: conflict-free.
// ---------------------------------------------------------------------------
#define AP 68
__global__ __launch_bounds__(128, 3)
void attn_tf32_kernel(const float* __restrict__ q, const float* __restrict__ k,
                      const float* __restrict__ v, const float* __restrict__ cg,
                      float* __restrict__ y) {
    __shared__ float KP[64][AP];   // K tile, then reused for P
    __shared__ float Vs[64][AP];
    __shared__ float cj[64];

    const int h = blockIdx.y, kvh = h >> 2;
    const int qt = blockIdx.x;
    const int i0 = qt << 6;
    const int tid = threadIdx.x, wid = tid >> 5, lane = tid & 31;
    const int grp = lane >> 2, tg = lane & 3;
    const int r0 = i0 + (wid << 4) + grp, r1 = r0 + 8;

    // Q fragments held in registers for the whole kernel
    uint32_t qa[8][4];
#pragma unroll
    for (int kt = 0; kt < 8; kt++) {
        const float* q0 = q + (size_t)r0 * C_DIM + h * 64 + (kt << 3);
        const float* q1 = q + (size_t)r1 * C_DIM + h * 64 + (kt << 3);
        qa[kt][0] = tf32r(q0[tg]);
        qa[kt][1] = tf32r(q1[tg]);
        qa[kt][2] = tf32r(q0[tg + 4]);
        qa[kt][3] = tf32r(q1[tg + 4]);
    }
    const float ci0 = cg[h * T_LEN + r0], ci1 = cg[h * T_LEN + r1];

    float m0 = NEG_BIG, m1 = NEG_BIG, l0 = 0.f, l1 = 0.f;
    float o[8][4] = {};

    for (int jt = 0; jt <= qt; jt++) {
        const int j0 = jt << 6;
        __syncthreads();
#pragma unroll
        for (int t = 0; t < 8; t++) {
            int idx = tid + (t << 7);
            int r = idx >> 4, c4 = (idx & 15) << 2;
            float4 kk = *(const float4*)(k + (size_t)(j0 + r) * KV_DIM + kvh * 64 + c4);
            *(float4*)&KP[r][c4] = tf32r4(kk);
            float4 vv = *(const float4*)(v + (size_t)(j0 + r) * KV_DIM + kvh * 64 + c4);
            *(float4*)&Vs[r][c4] = tf32r4(vv);
        }
        if (tid < 64) cj[tid] = cg[h * T_LEN + j0 + tid];
        __syncthreads();

        // S = Q K^T
        float s[8][4] = {};
#pragma unroll
        for (int kt = 0; kt < 8; kt++) {
#pragma unroll
            for (int nt = 0; nt < 8; nt++) {
                uint32_t b0 = __float_as_uint(KP[(nt << 3) + grp][(kt << 3) + tg]);
                uint32_t b1 = __float_as_uint(KP[(nt << 3) + grp][(kt << 3) + tg + 4]);
                mma_tf32(s[nt], qa[kt], b0, b1);
            }
        }

        // bias + causal mask + online softmax
        const bool diag = (jt == qt);
        float mt0 = NEG_BIG, mt1 = NEG_BIG;
#pragma unroll
        for (int nt = 0; nt < 8; nt++) {
            int c0 = (nt << 3) + (tg << 1), c1 = c0 + 1;
            float b0v = cj[c0], b1v = cj[c1];
            s[nt][0] = s[nt][0] * ATTN_SCALE + ci0 - b0v;
            s[nt][1] = s[nt][1] * ATTN_SCALE + ci0 - b1v;
            s[nt][2] = s[nt][2] * ATTN_SCALE + ci1 - b0v;
            s[nt][3] = s[nt][3] * ATTN_SCALE + ci1 - b1v;
            if (diag) {
                if (j0 + c0 > r0) s[nt][0] = NEG_BIG;
                if (j0 + c1 > r0) s[nt][1] = NEG_BIG;
                if (j0 + c0 > r1) s[nt][2] = NEG_BIG;
                if (j0 + c1 > r1) s[nt][3] = NEG_BIG;
            }
            mt0 = fmaxf(mt0, fmaxf(s[nt][0], s[nt][1]));
            mt1 = fmaxf(mt1, fmaxf(s[nt][2], s[nt][3]));
        }
        mt0 = fmaxf(mt0, __shfl_xor_sync(0xffffffffu, mt0, 1));
        mt0 = fmaxf(mt0, __shfl_xor_sync(0xffffffffu, mt0, 2));
        mt1 = fmaxf(mt1, __shfl_xor_sync(0xffffffffu, mt1, 1));
        mt1 = fmaxf(mt1, __shfl_xor_sync(0xffffffffu, mt1, 2));

        float mn0 = fmaxf(m0, mt0), mn1 = fmaxf(m1, mt1);
        float al0 = __expf(m0 - mn0), al1 = __expf(m1 - mn1);
        float ps0 = 0.f, ps1 = 0.f;
#pragma unroll
        for (int nt = 0; nt < 8; nt++) {
            s[nt][0] = __expf(s[nt][0] - mn0);
            s[nt][1] = __expf(s[nt][1] - mn0);
            s[nt][2] = __expf(s[nt][2] - mn1);
            s[nt][3] = __expf(s[nt][3] - mn1);
            ps0 += s[nt][0] + s[nt][1];
            ps1 += s[nt][2] + s[nt][3];
        }
        ps0 += __shfl_xor_sync(0xffffffffu, ps0, 1);
        ps0 += __shfl_xor_sync(0xffffffffu, ps0, 2);
        ps1 += __shfl_xor_sync(0xffffffffu, ps1, 1);
        ps1 += __shfl_xor_sync(0xffffffffu, ps1, 2);
        l0 = l0 * al0 + ps0;
        l1 = l1 * al1 + ps1;
        m0 = mn0; m1 = mn1;
#pragma unroll
        for (int nt = 0; nt < 8; nt++) {
            o[nt][0] *= al0; o[nt][1] *= al0;
            o[nt][2] *= al1; o[nt][3] *= al1;
        }

        __syncthreads();  // everyone done reading KP as K
        // store P into KP (warp-private 16 rows)
        const int pr0 = (wid << 4) + grp, pr1 = pr0 + 8;
#pragma unroll
        for (int nt = 0; nt < 8; nt++) {
            int c0 = (nt << 3) + (tg << 1);
            *(float2*)&KP[pr0][c0] = make_float2(
                __uint_as_float(tf32r(s[nt][0])), __uint_as_float(tf32r(s[nt][1])));
            *(float2*)&KP[pr1][c0] = make_float2(
                __uint_as_float(tf32r(s[nt][2])), __uint_as_float(tf32r(s[nt][3])));
        }
        __syncwarp();

        // O += P V
#pragma unroll
        for (int kt = 0; kt < 8; kt++) {
            uint32_t pa[4];
            pa[0] = __float_as_uint(KP[pr0 - grp + grp][(kt << 3) + tg]);      // row wid*16+grp
            pa[1] = __float_as_uint(KP[(wid << 4) + 8 + grp][(kt << 3) + tg]);
            pa[2] = __float_as_uint(KP[(wid << 4) + grp][(kt << 3) + tg + 4]);
            pa[3] = __float_as_uint(KP[(wid << 4) + 8 + grp][(kt << 3) + tg + 4]);
#pragma unroll
            for (int nt = 0; nt < 8; nt++) {
                uint32_t b0 = __float_as_uint(Vs[(kt << 3) + tg][(nt << 3) + grp]);
                uint32_t b1 = __float_as_uint(Vs[(kt << 3) + tg + 4][(nt << 3) + grp]);
                mma_tf32(o[nt], pa, b0, b1);
            }
        }
    }

    const float iv0 = 1.f / l0, iv1 = 1.f / l1;
#pragma unroll
    for (int nt = 0; nt < 8; nt++) {
        int col = h * 64 + (nt << 3) + (tg << 1);
        *(float2*)&y[(size_t)r0 * C_DIM + col] =
            make_float2(o[nt][0] * iv0, o[nt][1] * iv0);
        *(float2*)&y[(size_t)r1 * C_DIM + col] =
            make_float2(o[nt][2] * iv1, o[nt][3] * iv1);
    }
}

// ---------------------------------------------------------------------------
// kernel_launch
// ---------------------------------------------------------------------------
extern "C" void kernel_launch(void* const* d_in, const int* in_sizes, int n_in,
                              void* d_out, int out_size) {
    const float* x  = (const float*)d_in[0];
    const float* Wq = (const float*)d_in[1];
    const float* Wk = (const float*)d_in[2];
    const float* Wv = (const float*)d_in[3];
    const float* Wo = (const float*)d_in[4];
    const float* qw = (const float*)d_in[5];
    const float* kw = (const float*)d_in[6];
    const float* fg = (const float*)d_in[7];
    const float* fb = (const float*)d_in[8];
    const float* wl = (const float*)d_in[9];
    float* out = (float*)d_out;

    float *qp, *kp, *vp, *yp, *lfp, *cp;
    cudaGetSymbolAddress((void**)&qp, g_q);
    cudaGetSymbolAddress((void**)&kp, g_k);
    cudaGetSymbolAddress((void**)&vp, g_v);
    cudaGetSymbolAddress((void**)&yp, g_y);
    cudaGetSymbolAddress((void**)&lfp, g_logf);
    cudaGetSymbolAddress((void**)&cp, g_c);

    // Projections (tf32 tensor cores)
    gemm_tf32_kernel<<<dim3(C_DIM / 64, T_LEN / 128), 256>>>(x, Wq, qp, C_DIM, C_DIM);
    gemm_tf32_kernel<<<dim3(KV_DIM / 64, T_LEN / 128), 256>>>(x, Wk, kp, C_DIM, KV_DIM);
    gemm_tf32_kernel<<<dim3(KV_DIM / 64, T_LEN / 128), 256>>>(x, Wv, vp, C_DIM, KV_DIM);

    // RMSNorm + RoPE
    normrope_kernel<<<T_LEN, 256>>>(qp, kp, qw, kw);

    // Forgetting gate + cumsum
    gate_kernel<<<T_LEN, 128>>>(x, wl, fg, fb, lfp);
    scan_kernel<<<H_NUM, 32>>>(lfp, cp);

    // Flash attention (tf32 tensor cores)
    attn_tf32_kernel<<<dim3(T_LEN / 64, H_NUM), 128>>>(qp, kp, vp, cp, yp);

    // Output projection
    gemm_tf32_kernel<<<dim3(C_DIM / 64, T_LEN / 128), 256>>>(yp, Wo, out, C_DIM, C_DIM);
}

// round 3
// speedup vs baseline: 5.3498x; 1.1202x over previous
#include <cuda_runtime.h>
#include <math.h>
#include <stdint.h>

// Problem constants
#define T_LEN 2048
#define C_DIM 1024
#define H_NUM 16
#define KVH_NUM 4
#define D_DIM 64
#define KV_DIM 256
#define LOG2E 1.4426950408889634f
#define SCALE2 (0.125f * LOG2E)     // attn scale folded with log2(e)
#define NEG_BIG -1e30f

// Scratch (device globals: allocation-free)
__device__ float g_q[T_LEN * C_DIM];
__device__ float g_k[T_LEN * KV_DIM];
__device__ float g_v[T_LEN * KV_DIM];
__device__ float g_y[T_LEN * C_DIM];
__device__ float g_logf[H_NUM * T_LEN];
__device__ float g_c[H_NUM * T_LEN];    // cumsum * log2(e)

// ---------------------------------------------------------------------------
// helpers
// ---------------------------------------------------------------------------
__device__ __forceinline__ uint32_t tf32r(float x) {
    uint32_t u;
    asm("cvt.rna.tf32.f32 %0, %1;" : "=r"(u) : "f"(x));
    return u;
}
__device__ __forceinline__ float4 tf32r4(float4 v) {
    return make_float4(__uint_as_float(tf32r(v.x)), __uint_as_float(tf32r(v.y)),
                       __uint_as_float(tf32r(v.z)), __uint_as_float(tf32r(v.w)));
}
__device__ __forceinline__ float fex2(float x) {
    float r;
    asm("ex2.approx.ftz.f32 %0, %1;" : "=f"(r) : "f"(x));
    return r;
}
__device__ __forceinline__ void mma_tf32(float* c, const uint32_t* a,
                                         uint32_t b0, uint32_t b1) {
    asm volatile(
        "mma.sync.aligned.m16n8k8.row.col.f32.tf32.tf32.f32 "
        "{%0,%1,%2,%3}, {%4,%5,%6,%7}, {%8,%9}, {%0,%1,%2,%3};"
        : "+f"(c[0]), "+f"(c[1]), "+f"(c[2]), "+f"(c[3])
        : "r"(a[0]), "r"(a[1]), "r"(a[2]), "r"(a[3]), "r"(b0), "r"(b1));
}

// ---------------------------------------------------------------------------
// GEMM: O[M,N] = A[M,K] @ W[N,K]^T, tf32 mma.sync
// 128x128 block tile, BK=16, 256 threads, 64x32 warp tiles,
// 2-stage register-staged prefetch pipeline. blockIdx.z selects (W0,O0)/(W1,O1).
// ---------------------------------------------------------------------------
#define GSTR 20
__global__ __launch_bounds__(256, 1)
void gemm_tf32_kernel(const float* __restrict__ A,
                      const float* __restrict__ W0, float* __restrict__ O0,
                      const float* __restrict__ W1, float* __restrict__ O1,
                      int K, int N) {
    const float* W = blockIdx.z ? W1 : W0;
    float* O = blockIdx.z ? O1 : O0;
    __shared__ float As[2][128][GSTR];
    __shared__ float Ws[2][128][GSTR];
    const int m0 = blockIdx.y << 7, n0 = blockIdx.x << 7;
    const int tid = threadIdx.x, wid = tid >> 5, lane = tid & 31;
    const int grp = lane >> 2, tg = lane & 3;
    const int wm = (wid & 1) << 6, wn = (wid >> 1) << 5;
    const int ar = tid >> 2, ac = (tid & 3) << 2;

    const float* Abase = A + (size_t)(m0 + ar) * K + ac;
    const float* Wbase = W + (size_t)(n0 + ar) * K + ac;

    float acc[4][4][4] = {};

    {   // preload stage 0
        float4 a0 = *(const float4*)(Abase);
        float4 a1 = *(const float4*)(Abase + (size_t)64 * K);
        float4 w0 = *(const float4*)(Wbase);
        float4 w1 = *(const float4*)(Wbase + (size_t)64 * K);
        *(float4*)&As[0][ar][ac] = tf32r4(a0);
        *(float4*)&As[0][ar + 64][ac] = tf32r4(a1);
        *(float4*)&Ws[0][ar][ac] = tf32r4(w0);
        *(float4*)&Ws[0][ar + 64][ac] = tf32r4(w1);
    }
    __syncthreads();

    const int NK = K >> 4;
#pragma unroll 2
    for (int ks = 0; ks < NK; ks++) {
        const int s = ks & 1;
        float4 a0, a1, w0, w1;
        const bool has = (ks + 1 < NK);
        if (has) {   // prefetch next tile into registers (overlaps MMA below)
            const float* ap = Abase + (ks + 1) * 16;
            const float* wp = Wbase + (ks + 1) * 16;
            a0 = *(const float4*)(ap);
            a1 = *(const float4*)(ap + (size_t)64 * K);
            w0 = *(const float4*)(wp);
            w1 = *(const float4*)(wp + (size_t)64 * K);
        }
#pragma unroll
        for (int kb = 0; kb < 16; kb += 8) {
            uint32_t af[4][4];
#pragma unroll
            for (int mt = 0; mt < 4; mt++) {
                int mr = wm + (mt << 4);
                af[mt][0] = __float_as_uint(As[s][mr + grp][kb + tg]);
                af[mt][1] = __float_as_uint(As[s][mr + 8 + grp][kb + tg]);
                af[mt][2] = __float_as_uint(As[s][mr + grp][kb + tg + 4]);
                af[mt][3] = __float_as_uint(As[s][mr + 8 + grp][kb + tg + 4]);
            }
#pragma unroll
            for (int nt = 0; nt < 4; nt++) {
                int nc = wn + (nt << 3);
                uint32_t b0 = __float_as_uint(Ws[s][nc + grp][kb + tg]);
                uint32_t b1 = __float_as_uint(Ws[s][nc + grp][kb + tg + 4]);
#pragma unroll
                for (int mt = 0; mt < 4; mt++)
                    mma_tf32(acc[mt][nt], af[mt], b0, b1);
            }
        }
        if (has) {
            *(float4*)&As[s ^ 1][ar][ac] = tf32r4(a0);
            *(float4*)&As[s ^ 1][ar + 64][ac] = tf32r4(a1);
            *(float4*)&Ws[s ^ 1][ar][ac] = tf32r4(w0);
            *(float4*)&Ws[s ^ 1][ar + 64][ac] = tf32r4(w1);
        }
        __syncthreads();
    }
#pragma unroll
    for (int mt = 0; mt < 4; mt++)
#pragma unroll
        for (int nt = 0; nt < 4; nt++) {
            int row = m0 + wm + (mt << 4) + grp;
            int col = n0 + wn + (nt << 3) + (tg << 1);
            *(float2*)&O[(size_t)row * N + col] =
                make_float2(acc[mt][nt][0], acc[mt][nt][1]);
            *(float2*)&O[(size_t)(row + 8) * N + col] =
                make_float2(acc[mt][nt][2], acc[mt][nt][3]);
        }
}

// ---------------------------------------------------------------------------
// RMSNorm + RoPE, in place, q and k (one block per token). ex2-based inv_freq.
// ---------------------------------------------------------------------------
__global__ void normrope_kernel(float* __restrict__ q, float* __restrict__ k,
                                const float* __restrict__ qw,
                                const float* __restrict__ kw) {
    const int t = blockIdx.x;
    const int tid = threadIdx.x;
    __shared__ float buf[C_DIM];
    __shared__ float red[8];
    __shared__ float s_inv;

    float ss = 0.f;
    for (int c = tid; c < C_DIM; c += 256) {
        float vv = q[(size_t)t * C_DIM + c];
        buf[c] = vv;
        ss += vv * vv;
    }
#pragma unroll
    for (int o = 16; o; o >>= 1) ss += __shfl_xor_sync(0xffffffffu, ss, o);
    if ((tid & 31) == 0) red[tid >> 5] = ss;
    __syncthreads();
    if (tid == 0) {
        float tot = 0.f;
#pragma unroll
        for (int w = 0; w < 8; w++) tot += red[w];
        s_inv = rsqrtf(tot / (float)C_DIM + 1e-6f);
    }
    __syncthreads();
    float inv = s_inv;
    for (int c = tid; c < C_DIM; c += 256) {
        int d = c & 63;
        float xn = buf[c] * inv * qw[c];
        float other;
        int f;
        if (d < 32) { other = -buf[c + 32] * inv * qw[c + 32]; f = d; }
        else        { other =  buf[c - 32] * inv * qw[c - 32]; f = d - 32; }
        // theta = t * 10000^(-f/32) = t * exp2(-f * log2(1e4)/32)
        float th = (float)t * fex2((float)f * -0.41524101186092029f);
        q[(size_t)t * C_DIM + c] = xn * cosf(th) + other * sinf(th);
    }
    __syncthreads();

    float ss2 = 0.f;
    if (tid < KV_DIM) {
        float vv = k[(size_t)t * KV_DIM + tid];
        buf[tid] = vv;
        ss2 = vv * vv;
    }
#pragma unroll
    for (int o = 16; o; o >>= 1) ss2 += __shfl_xor_sync(0xffffffffu, ss2, o);
    if ((tid & 31) == 0) red[tid >> 5] = ss2;
    __syncthreads();
    if (tid == 0) {
        float tot = 0.f;
#pragma unroll
        for (int w = 0; w < 8; w++) tot += red[w];
        s_inv = rsqrtf(tot / (float)KV_DIM + 1e-6f);
    }
    __syncthreads();
    inv = s_inv;
    if (tid < KV_DIM) {
        int c = tid;
        int d = c & 63;
        float xn = buf[c] * inv * kw[c];
        float other;
        int f;
        if (d < 32) { other = -buf[c + 32] * inv * kw[c + 32]; f = d; }
        else        { other =  buf[c - 32] * inv * kw[c - 32]; f = d - 32; }
        float th = (float)t * fex2((float)f * -0.41524101186092029f);
        k[(size_t)t * KV_DIM + c] = xn * cosf(th) + other * sinf(th);
    }
}

// ---------------------------------------------------------------------------
// Forgetting gate, 8 tokens per block (weights read once per 8 tokens).
// 256 threads = 16 heads x 16 lanes.
// ---------------------------------------------------------------------------
__global__ __launch_bounds__(256, 2)
void gate_kernel(const float* __restrict__ x,
                 const float* __restrict__ wl,   // [C, H]
                 const float* __restrict__ fg,   // [H, C]
                 const float* __restrict__ fb,   // [H]
                 float* __restrict__ logf_out) { // [H, T]
    __shared__ float xs[8][C_DIM];
    const int t0 = blockIdx.x << 3;
    const int tid = threadIdx.x;
    for (int i = tid; i < 8 * C_DIM; i += 256)
        xs[i >> 10][i & 1023] = x[(size_t)t0 * C_DIM + i];
    __syncthreads();

    const int h = tid >> 4, l16 = tid & 15;
    float z1[8] = {}, z2[8] = {};
    for (int c = l16; c < C_DIM; c += 16) {
        float wlv = wl[(size_t)c * H_NUM + h];
        float fgv = fg[(size_t)h * C_DIM + c];
#pragma unroll
        for (int g = 0; g < 8; g++) {
            float xv = xs[g][c];
            z1[g] += xv * wlv;
            z2[g] += xv * fgv;
        }
    }
#pragma unroll
    for (int o = 8; o; o >>= 1) {
#pragma unroll
        for (int g = 0; g < 8; g++) {
            z1[g] += __shfl_xor_sync(0xffffffffu, z1[g], o);
            z2[g] += __shfl_xor_sync(0xffffffffu, z2[g], o);
        }
    }
    if (l16 == 0) {
        float fbv = fb[h];
#pragma unroll
        for (int g = 0; g < 8; g++) {
            float lam = (z1[g] > 0.f ? z1[g] : expf(z1[g]) - 1.f) + 1.f;
            float logit = (z2[g] + fbv) * lam;
            float ls = (logit >= 0.f) ? -log1pf(expf(-logit))
                                      : (logit - log1pf(expf(logit)));
            logf_out[(size_t)h * T_LEN + t0 + g] = ls / (lam + 1e-3f);
        }
    }
}

// ---------------------------------------------------------------------------
// Per-head inclusive cumsum, scaled by log2(e) for exp2-domain softmax.
// ---------------------------------------------------------------------------
__global__ void scan_kernel(const float* __restrict__ lf, float* __restrict__ c) {
    const int h = blockIdx.x;
    const int lane = threadIdx.x;
    const float* src = lf + (size_t)h * T_LEN;
    float* dst = c + (size_t)h * T_LEN;
    const int base = lane * 64;
    float s = 0.f;
#pragma unroll 8
    for (int i = 0; i < 64; i++) s += src[base + i];
    float incl = s;
#pragma unroll
    for (int o = 1; o < 32; o <<= 1) {
        float vv = __shfl_up_sync(0xffffffffu, incl, o);
        if (lane >= o) incl += vv;
    }
    float run = incl - s;
#pragma unroll 8
    for (int i = 0; i < 64; i++) {
        run += src[base + i];
        dst[base + i] = run * LOG2E;
    }
}

// ---------------------------------------------------------------------------
// Flash attention via tf32 mma.sync, exp2-domain online softmax.
// 64 queries x 64 keys per tile, 4 warps x 16 rows.
// ---------------------------------------------------------------------------
#define AP 68
__global__ __launch_bounds__(128, 3)
void attn_tf32_kernel(const float* __restrict__ q, const float* __restrict__ k,
                      const float* __restrict__ v, const float* __restrict__ cg,
                      float* __restrict__ y) {
    __shared__ float KP[64][AP];   // K tile, then reused for P
    __shared__ float Vs[64][AP];
    __shared__ float cj[64];

    const int h = blockIdx.y, kvh = h >> 2;
    const int qt = blockIdx.x;
    const int i0 = qt << 6;
    const int tid = threadIdx.x, wid = tid >> 5, lane = tid & 31;
    const int grp = lane >> 2, tg = lane & 3;
    const int r0 = i0 + (wid << 4) + grp, r1 = r0 + 8;

    uint32_t qa[8][4];
#pragma unroll
    for (int kt = 0; kt < 8; kt++) {
        const float* q0 = q + (size_t)r0 * C_DIM + h * 64 + (kt << 3);
        const float* q1 = q + (size_t)r1 * C_DIM + h * 64 + (kt << 3);
        qa[kt][0] = tf32r(q0[tg]);
        qa[kt][1] = tf32r(q1[tg]);
        qa[kt][2] = tf32r(q0[tg + 4]);
        qa[kt][3] = tf32r(q1[tg + 4]);
    }
    const float ci0 = cg[h * T_LEN + r0], ci1 = cg[h * T_LEN + r1];

    float m0 = NEG_BIG, m1 = NEG_BIG, l0 = 0.f, l1 = 0.f;
    float o[8][4] = {};

    for (int jt = 0; jt <= qt; jt++) {
        const int j0 = jt << 6;
        __syncthreads();
#pragma unroll
        for (int t = 0; t < 8; t++) {
            int idx = tid + (t << 7);
            int r = idx >> 4, c4 = (idx & 15) << 2;
            float4 kk = *(const float4*)(k + (size_t)(j0 + r) * KV_DIM + kvh * 64 + c4);
            *(float4*)&KP[r][c4] = tf32r4(kk);
            float4 vv = *(const float4*)(v + (size_t)(j0 + r) * KV_DIM + kvh * 64 + c4);
            *(float4*)&Vs[r][c4] = tf32r4(vv);
        }
        if (tid < 64) cj[tid] = cg[h * T_LEN + j0 + tid];
        __syncthreads();

        float s[8][4] = {};
#pragma unroll
        for (int kt = 0; kt < 8; kt++) {
#pragma unroll
            for (int nt = 0; nt < 8; nt++) {
                uint32_t b0 = __float_as_uint(KP[(nt << 3) + grp][(kt << 3) + tg]);
                uint32_t b1 = __float_as_uint(KP[(nt << 3) + grp][(kt << 3) + tg + 4]);
                mma_tf32(s[nt], qa[kt], b0, b1);
            }
        }

        const bool diag = (jt == qt);
        float mt0 = NEG_BIG, mt1 = NEG_BIG;
#pragma unroll
        for (int nt = 0; nt < 8; nt++) {
            int c0 = (nt << 3) + (tg << 1), c1 = c0 + 1;
            float b0v = cj[c0], b1v = cj[c1];
            s[nt][0] = s[nt][0] * SCALE2 + ci0 - b0v;
            s[nt][1] = s[nt][1] * SCALE2 + ci0 - b1v;
            s[nt][2] = s[nt][2] * SCALE2 + ci1 - b0v;
            s[nt][3] = s[nt][3] * SCALE2 + ci1 - b1v;
            if (diag) {
                if (j0 + c0 > r0) s[nt][0] = NEG_BIG;
                if (j0 + c1 > r0) s[nt][1] = NEG_BIG;
                if (j0 + c0 > r1) s[nt][2] = NEG_BIG;
                if (j0 + c1 > r1) s[nt][3] = NEG_BIG;
            }
            mt0 = fmaxf(mt0, fmaxf(s[nt][0], s[nt][1]));
            mt1 = fmaxf(mt1, fmaxf(s[nt][2], s[nt][3]));
        }
        mt0 = fmaxf(mt0, __shfl_xor_sync(0xffffffffu, mt0, 1));
        mt0 = fmaxf(mt0, __shfl_xor_sync(0xffffffffu, mt0, 2));
        mt1 = fmaxf(mt1, __shfl_xor_sync(0xffffffffu, mt1, 1));
        mt1 = fmaxf(mt1, __shfl_xor_sync(0xffffffffu, mt1, 2));

        float mn0 = fmaxf(m0, mt0), mn1 = fmaxf(m1, mt1);
        float al0 = fex2(m0 - mn0), al1 = fex2(m1 - mn1);
        float ps0 = 0.f, ps1 = 0.f;
#pragma unroll
        for (int nt = 0; nt < 8; nt++) {
            s[nt][0] = fex2(s[nt][0] - mn0);
            s[nt][1] = fex2(s[nt][1] - mn0);
            s[nt][2] = fex2(s[nt][2] - mn1);
            s[nt][3] = fex2(s[nt][3] - mn1);
            ps0 += s[nt][0] + s[nt][1];
            ps1 += s[nt][2] + s[nt][3];
        }
        ps0 += __shfl_xor_sync(0xffffffffu, ps0, 1);
        ps0 += __shfl_xor_sync(0xffffffffu, ps0, 2);
        ps1 += __shfl_xor_sync(0xffffffffu, ps1, 1);
        ps1 += __shfl_xor_sync(0xffffffffu, ps1, 2);
        l0 = l0 * al0 + ps0;
        l1 = l1 * al1 + ps1;
        m0 = mn0; m1 = mn1;
#pragma unroll
        for (int nt = 0; nt < 8; nt++) {
            o[nt][0] *= al0; o[nt][1] *= al0;
            o[nt][2] *= al1; o[nt][3] *= al1;
        }

        __syncthreads();  // done reading KP as K
        const int pr0 = (wid << 4) + grp, pr1 = pr0 + 8;
#pragma unroll
        for (int nt = 0; nt < 8; nt++) {
            int c0 = (nt << 3) + (tg << 1);
            *(float2*)&KP[pr0][c0] = make_float2(
                __uint_as_float(tf32r(s[nt][0])), __uint_as_float(tf32r(s[nt][1])));
            *(float2*)&KP[pr1][c0] = make_float2(
                __uint_as_float(tf32r(s[nt][2])), __uint_as_float(tf32r(s[nt][3])));
        }
        __syncwarp();

#pragma unroll
        for (int kt = 0; kt < 8; kt++) {
            uint32_t pa[4];
            pa[0] = __float_as_uint(KP[pr0][(kt << 3) + tg]);
            pa[1] = __float_as_uint(KP[pr1][(kt << 3) + tg]);
            pa[2] = __float_as_uint(KP[pr0][(kt << 3) + tg + 4]);
            pa[3] = __float_as_uint(KP[pr1][(kt << 3) + tg + 4]);
#pragma unroll
            for (int nt = 0; nt < 8; nt++) {
                uint32_t b0 = __float_as_uint(Vs[(kt << 3) + tg][(nt << 3) + grp]);
                uint32_t b1 = __float_as_uint(Vs[(kt << 3) + tg + 4][(nt << 3) + grp]);
                mma_tf32(o[nt], pa, b0, b1);
            }
        }
    }

    const float iv0 = 1.f / l0, iv1 = 1.f / l1;
#pragma unroll
    for (int nt = 0; nt < 8; nt++) {
        int col = h * 64 + (nt << 3) + (tg << 1);
        *(float2*)&y[(size_t)r0 * C_DIM + col] =
            make_float2(o[nt][0] * iv0, o[nt][1] * iv0);
        *(float2*)&y[(size_t)r1 * C_DIM + col] =
            make_float2(o[nt][2] * iv1, o[nt][3] * iv1);
    }
}

// ---------------------------------------------------------------------------
// kernel_launch — attn is launch index 5 so the ncu capture (-s 5) lands on it
// ---------------------------------------------------------------------------
extern "C" void kernel_launch(void* const* d_in, const int* in_sizes, int n_in,
                              void* d_out, int out_size) {
    const float* x  = (const float*)d_in[0];
    const float* Wq = (const float*)d_in[1];
    const float* Wk = (const float*)d_in[2];
    const float* Wv = (const float*)d_in[3];
    const float* Wo = (const float*)d_in[4];
    const float* qw = (const float*)d_in[5];
    const float* kw = (const float*)d_in[6];
    const float* fg = (const float*)d_in[7];
    const float* fb = (const float*)d_in[8];
    const float* wl = (const float*)d_in[9];
    float* out = (float*)d_out;

    float *qp, *kp, *vp, *yp, *lfp, *cp;
    cudaGetSymbolAddress((void**)&qp, g_q);
    cudaGetSymbolAddress((void**)&kp, g_k);
    cudaGetSymbolAddress((void**)&vp, g_v);
    cudaGetSymbolAddress((void**)&yp, g_y);
    cudaGetSymbolAddress((void**)&lfp, g_logf);
    cudaGetSymbolAddress((void**)&cp, g_c);

    // 0-1: gate + cumsum (x only)
    gate_kernel<<<T_LEN / 8, 256>>>(x, wl, fg, fb, lfp);
    scan_kernel<<<H_NUM, 32>>>(lfp, cp);

    // 2: Q projection
    gemm_tf32_kernel<<<dim3(C_DIM / 128, T_LEN / 128, 1), 256>>>(
        x, Wq, qp, Wq, qp, C_DIM, C_DIM);
    // 3: fused K/V projections (z selects)
    gemm_tf32_kernel<<<dim3(KV_DIM / 128, T_LEN / 128, 2), 256>>>(
        x, Wk, kp, Wv, vp, C_DIM, KV_DIM);

    // 4: RMSNorm + RoPE
    normrope_kernel<<<T_LEN, 256>>>(qp, kp, qw, kw);

    // 5: flash attention (profiled launch)
    attn_tf32_kernel<<<dim3(T_LEN / 64, H_NUM), 128>>>(qp, kp, vp, cp, yp);

    // 6: output projection
    gemm_tf32_kernel<<<dim3(C_DIM / 128, T_LEN / 128, 1), 256>>>(
        yp, Wo, out, Wo, out, C_DIM, C_DIM);
}

// round 5
// speedup vs baseline: 5.4799x; 1.0243x over previous
#include <cuda_runtime.h>
#include <math.h>
#include <stdint.h>

// Problem constants
#define T_LEN 2048
#define C_DIM 1024
#define H_NUM 16
#define KVH_NUM 4
#define D_DIM 64
#define KV_DIM 256
#define LOG2E 1.4426950408889634f
#define SCALE2 (0.125f * LOG2E)
#define NEG_BIG -1e30f

// Scratch
__device__ float g_q[T_LEN * C_DIM];
__device__ float g_k[T_LEN * KV_DIM];
__device__ float g_v[T_LEN * KV_DIM];
__device__ float g_y[T_LEN * C_DIM];
__device__ float g_logf[H_NUM * T_LEN];
__device__ float g_c[H_NUM * T_LEN];

// ---------------------------------------------------------------------------
// helpers
// ---------------------------------------------------------------------------
__device__ __forceinline__ uint32_t tf32r(float x) {
    uint32_t u;
    asm("cvt.rna.tf32.f32 %0, %1;" : "=r"(u) : "f"(x));
    return u;
}
__device__ __forceinline__ float4 tf32r4(float4 v) {
    return make_float4(__uint_as_float(tf32r(v.x)), __uint_as_float(tf32r(v.y)),
                       __uint_as_float(tf32r(v.z)), __uint_as_float(tf32r(v.w)));
}
__device__ __forceinline__ float fex2(float x) {
    float r;
    asm("ex2.approx.ftz.f32 %0, %1;" : "=f"(r) : "f"(x));
    return r;
}
__device__ __forceinline__ void mma_tf32(float* c, const uint32_t* a,
                                         uint32_t b0, uint32_t b1) {
    asm volatile(
        "mma.sync.aligned.m16n8k8.row.col.f32.tf32.tf32.f32 "
        "{%0,%1,%2,%3}, {%4,%5,%6,%7}, {%8,%9}, {%0,%1,%2,%3};"
        : "+f"(c[0]), "+f"(c[1]), "+f"(c[2]), "+f"(c[3])
        : "r"(a[0]), "r"(a[1]), "r"(a[2]), "r"(a[3]), "r"(b0), "r"(b1));
}

// ---------------------------------------------------------------------------
// GEMM v3: O[M,N] = A[M,K] @ W[N,K]^T
// Block tile 128x64, BK=16, 256 threads, 8 warps of 32x32, 2 CTAs/SM.
// fused=1: n-tile index selects Wq/Wk/Wv (24 n-tiles: 16 Q + 4 K + 4 V).
// ---------------------------------------------------------------------------
#define GSTR 20
__global__ __launch_bounds__(256, 2)
void gemm_tf32_kernel(const float* __restrict__ A,
                      const float* __restrict__ Wq, float* __restrict__ Oq,
                      const float* __restrict__ Wk, float* __restrict__ Ok,
                      const float* __restrict__ Wv, float* __restrict__ Ov,
                      int K, int fused) {
    __shared__ float As[2][128][GSTR];
    __shared__ float Ws[2][64][GSTR];

    const int bx = blockIdx.x;
    const float* W;
    float* O;
    int n0, Nout;
    if (fused && bx >= 16) {
        if (bx < 20) { W = Wk; O = Ok; n0 = (bx - 16) << 6; }
        else         { W = Wv; O = Ov; n0 = (bx - 20) << 6; }
        Nout = KV_DIM;
    } else {
        W = Wq; O = Oq; n0 = bx << 6; Nout = C_DIM;
    }
    const int m0 = blockIdx.y << 7;
    const int tid = threadIdx.x, wid = tid >> 5, lane = tid & 31;
    const int grp = lane >> 2, tg = lane & 3;
    const int wm = (wid & 3) << 5, wn = (wid >> 2) << 5;
    const int ar = tid >> 2, ac = (tid & 3) << 2;

    const float* Abase = A + (size_t)(m0 + ar) * K + ac;
    const float* Wbase = W + (size_t)(n0 + ar) * K + ac;

    float acc[2][4][4] = {};

    {   // preload stage 0
        float4 a0 = *(const float4*)(Abase);
        float4 a1 = *(const float4*)(Abase + (size_t)64 * K);
        float4 w0 = *(const float4*)(Wbase);
        *(float4*)&As[0][ar][ac] = tf32r4(a0);
        *(float4*)&As[0][ar + 64][ac] = tf32r4(a1);
        *(float4*)&Ws[0][ar][ac] = tf32r4(w0);
    }
    __syncthreads();

    const int NK = K >> 4;
#pragma unroll 2
    for (int ks = 0; ks < NK; ks++) {
        const int s = ks & 1;
        float4 a0, a1, w0;
        const bool has = (ks + 1 < NK);
        if (has) {
            const float* ap = Abase + (ks + 1) * 16;
            const float* wp = Wbase + (ks + 1) * 16;
            a0 = *(const float4*)(ap);
            a1 = *(const float4*)(ap + (size_t)64 * K);
            w0 = *(const float4*)(wp);
        }
#pragma unroll
        for (int kb = 0; kb < 16; kb += 8) {
            uint32_t af[2][4];
#pragma unroll
            for (int mt = 0; mt < 2; mt++) {
                int mr = wm + (mt << 4);
                af[mt][0] = __float_as_uint(As[s][mr + grp][kb + tg]);
                af[mt][1] = __float_as_uint(As[s][mr + 8 + grp][kb + tg]);
                af[mt][2] = __float_as_uint(As[s][mr + grp][kb + tg + 4]);
                af[mt][3] = __float_as_uint(As[s][mr + 8 + grp][kb + tg + 4]);
            }
#pragma unroll
            for (int nt = 0; nt < 4; nt++) {
                int nc = wn + (nt << 3);
                uint32_t b0 = __float_as_uint(Ws[s][nc + grp][kb + tg]);
                uint32_t b1 = __float_as_uint(Ws[s][nc + grp][kb + tg + 4]);
                mma_tf32(acc[0][nt], af[0], b0, b1);
                mma_tf32(acc[1][nt], af[1], b0, b1);
            }
        }
        if (has) {
            *(float4*)&As[s ^ 1][ar][ac] = tf32r4(a0);
            *(float4*)&As[s ^ 1][ar + 64][ac] = tf32r4(a1);
            *(float4*)&Ws[s ^ 1][ar][ac] = tf32r4(w0);
        }
        __syncthreads();
    }
#pragma unroll
    for (int mt = 0; mt < 2; mt++)
#pragma unroll
        for (int nt = 0; nt < 4; nt++) {
            int row = m0 + wm + (mt << 4) + grp;
            int col = n0 + wn + (nt << 3) + (tg << 1);
            *(float2*)&O[(size_t)row * Nout + col] =
                make_float2(acc[mt][nt][0], acc[mt][nt][1]);
            *(float2*)&O[(size_t)(row + 8) * Nout + col] =
                make_float2(acc[mt][nt][2], acc[mt][nt][3]);
        }
}

// ---------------------------------------------------------------------------
// RMSNorm + RoPE, in place. 32 sincos per token via smem table (was 1280).
// ---------------------------------------------------------------------------
__global__ void normrope_kernel(float* __restrict__ q, float* __restrict__ k,
                                const float* __restrict__ qw,
                                const float* __restrict__ kw) {
    const int t = blockIdx.x;
    const int tid = threadIdx.x;
    __shared__ float buf[C_DIM];
    __shared__ float cs[32], sn[32];
    __shared__ float red[8];
    __shared__ float s_inv;

    if (tid < 32) {
        // theta = t * 10000^(-tid/32) = t * exp2(tid * -log2(1e4)/32)
        float th = (float)t * fex2((float)tid * -0.41524101186092029f);
        cs[tid] = cosf(th);
        sn[tid] = sinf(th);
    }

    float ss = 0.f;
    for (int c = tid; c < C_DIM; c += 256) {
        float vv = q[(size_t)t * C_DIM + c];
        buf[c] = vv;
        ss += vv * vv;
    }
#pragma unroll
    for (int o = 16; o; o >>= 1) ss += __shfl_xor_sync(0xffffffffu, ss, o);
    if ((tid & 31) == 0) red[tid >> 5] = ss;
    __syncthreads();
    if (tid == 0) {
        float tot = 0.f;
#pragma unroll
        for (int w = 0; w < 8; w++) tot += red[w];
        s_inv = rsqrtf(tot / (float)C_DIM + 1e-6f);
    }
    __syncthreads();
    float inv = s_inv;
    for (int c = tid; c < C_DIM; c += 256) {
        int d = c & 63;
        int f = d & 31;
        float xn = buf[c] * inv * qw[c];
        float other = (d < 32) ? -buf[c + 32] * inv * qw[c + 32]
                               :  buf[c - 32] * inv * qw[c - 32];
        q[(size_t)t * C_DIM + c] = xn * cs[f] + other * sn[f];
    }
    __syncthreads();

    float ss2 = 0.f;
    if (tid < KV_DIM) {
        float vv = k[(size_t)t * KV_DIM + tid];
        buf[tid] = vv;
        ss2 = vv * vv;
    }
#pragma unroll
    for (int o = 16; o; o >>= 1) ss2 += __shfl_xor_sync(0xffffffffu, ss2, o);
    if ((tid & 31) == 0) red[tid >> 5] = ss2;
    __syncthreads();
    if (tid == 0) {
        float tot = 0.f;
#pragma unroll
        for (int w = 0; w < 8; w++) tot += red[w];
        s_inv = rsqrtf(tot / (float)KV_DIM + 1e-6f);
    }
    __syncthreads();
    inv = s_inv;
    if (tid < KV_DIM) {
        int c = tid;
        int d = c & 63;
        int f = d & 31;
        float xn = buf[c] * inv * kw[c];
        float other = (d < 32) ? -buf[c + 32] * inv * kw[c + 32]
                               :  buf[c - 32] * inv * kw[c - 32];
        k[(size_t)t * KV_DIM + c] = xn * cs[f] + other * sn[f];
    }
}

// ---------------------------------------------------------------------------
// Forgetting gate, 8 tokens per block.
// ---------------------------------------------------------------------------
__global__ __launch_bounds__(256, 2)
void gate_kernel(const float* __restrict__ x,
                 const float* __restrict__ wl,
                 const float* __restrict__ fg,
                 const float* __restrict__ fb,
                 float* __restrict__ logf_out) {
    __shared__ float xs[8][C_DIM];
    const int t0 = blockIdx.x << 3;
    const int tid = threadIdx.x;
    for (int i = tid; i < 8 * C_DIM; i += 256)
        xs[i >> 10][i & 1023] = x[(size_t)t0 * C_DIM + i];
    __syncthreads();

    const int h = tid >> 4, l16 = tid & 15;
    float z1[8] = {}, z2[8] = {};
    for (int c = l16; c < C_DIM; c += 16) {
        float wlv = wl[(size_t)c * H_NUM + h];
        float fgv = fg[(size_t)h * C_DIM + c];
#pragma unroll
        for (int g = 0; g < 8; g++) {
            float xv = xs[g][c];
            z1[g] += xv * wlv;
            z2[g] += xv * fgv;
        }
    }
#pragma unroll
    for (int o = 8; o; o >>= 1) {
#pragma unroll
        for (int g = 0; g < 8; g++) {
            z1[g] += __shfl_xor_sync(0xffffffffu, z1[g], o);
            z2[g] += __shfl_xor_sync(0xffffffffu, z2[g], o);
        }
    }
    if (l16 == 0) {
        float fbv = fb[h];
#pragma unroll
        for (int g = 0; g < 8; g++) {
            float lam = (z1[g] > 0.f ? z1[g] : expf(z1[g]) - 1.f) + 1.f;
            float logit = (z2[g] + fbv) * lam;
            float ls = (logit >= 0.f) ? -log1pf(expf(-logit))
                                      : (logit - log1pf(expf(logit)));
            logf_out[(size_t)h * T_LEN + t0 + g] = ls / (lam + 1e-3f);
        }
    }
}

// ---------------------------------------------------------------------------
// Per-head inclusive cumsum (scaled by log2 e).
// ---------------------------------------------------------------------------
__global__ void scan_kernel(const float* __restrict__ lf, float* __restrict__ c) {
    const int h = blockIdx.x;
    const int lane = threadIdx.x;
    const float* src = lf + (size_t)h * T_LEN;
    float* dst = c + (size_t)h * T_LEN;
    const int base = lane * 64;
    float s = 0.f;
#pragma unroll 8
    for (int i = 0; i < 64; i++) s += src[base + i];
    float incl = s;
#pragma unroll
    for (int o = 1; o < 32; o <<= 1) {
        float vv = __shfl_up_sync(0xffffffffu, incl, o);
        if (lane >= o) incl += vv;
    }
    float run = incl - s;
#pragma unroll 8
    for (int i = 0; i < 64; i++) {
        run += src[base + i];
        dst[base + i] = run * LOG2E;
    }
}

// ---------------------------------------------------------------------------
// Flash attention (tf32 mma, exp2-domain softmax).
// ---------------------------------------------------------------------------
#define AP 68
__global__ __launch_bounds__(128, 3)
void attn_tf32_kernel(const float* __restrict__ q, const float* __restrict__ k,
                      const float* __restrict__ v, const float* __restrict__ cg,
                      float* __restrict__ y) {
    __shared__ float KP[64][AP];
    __shared__ float Vs[64][AP];
    __shared__ float cj[64];

    const int h = blockIdx.y, kvh = h >> 2;
    const int qt = blockIdx.x;
    const int i0 = qt << 6;
    const int tid = threadIdx.x, wid = tid >> 5, lane = tid & 31;
    const int grp = lane >> 2, tg = lane & 3;
    const int r0 = i0 + (wid << 4) + grp, r1 = r0 + 8;

    uint32_t qa[8][4];
#pragma unroll
    for (int kt = 0; kt < 8; kt++) {
        const float* q0 = q + (size_t)r0 * C_DIM + h * 64 + (kt << 3);
        const float* q1 = q + (size_t)r1 * C_DIM + h * 64 + (kt << 3);
        qa[kt][0] = tf32r(q0[tg]);
        qa[kt][1] = tf32r(q1[tg]);
        qa[kt][2] = tf32r(q0[tg + 4]);
        qa[kt][3] = tf32r(q1[tg + 4]);
    }
    const float ci0 = cg[h * T_LEN + r0], ci1 = cg[h * T_LEN + r1];

    float m0 = NEG_BIG, m1 = NEG_BIG, l0 = 0.f, l1 = 0.f;
    float o[8][4] = {};

    for (int jt = 0; jt <= qt; jt++) {
        const int j0 = jt << 6;
        __syncthreads();
#pragma unroll
        for (int t = 0; t < 8; t++) {
            int idx = tid + (t << 7);
            int r = idx >> 4, c4 = (idx & 15) << 2;
            float4 kk = *(const float4*)(k + (size_t)(j0 + r) * KV_DIM + kvh * 64 + c4);
            *(float4*)&KP[r][c4] = tf32r4(kk);
            float4 vv = *(const float4*)(v + (size_t)(j0 + r) * KV_DIM + kvh * 64 + c4);
            *(float4*)&Vs[r][c4] = tf32r4(vv);
        }
        if (tid < 64) cj[tid] = cg[h * T_LEN + j0 + tid];
        __syncthreads();

        float s[8][4] = {};
#pragma unroll
        for (int kt = 0; kt < 8; kt++) {
#pragma unroll
            for (int nt = 0; nt < 8; nt++) {
                uint32_t b0 = __float_as_uint(KP[(nt << 3) + grp][(kt << 3) + tg]);
                uint32_t b1 = __float_as_uint(KP[(nt << 3) + grp][(kt << 3) + tg + 4]);
                mma_tf32(s[nt], qa[kt], b0, b1);
            }
        }

        const bool diag = (jt == qt);
        float mt0 = NEG_BIG, mt1 = NEG_BIG;
#pragma unroll
        for (int nt = 0; nt < 8; nt++) {
            int c0 = (nt << 3) + (tg << 1), c1 = c0 + 1;
            float b0v = cj[c0], b1v = cj[c1];
            s[nt][0] = s[nt][0] * SCALE2 + ci0 - b0v;
            s[nt][1] = s[nt][1] * SCALE2 + ci0 - b1v;
            s[nt][2] = s[nt][2] * SCALE2 + ci1 - b0v;
            s[nt][3] = s[nt][3] * SCALE2 + ci1 - b1v;
            if (diag) {
                if (j0 + c0 > r0) s[nt][0] = NEG_BIG;
                if (j0 + c1 > r0) s[nt][1] = NEG_BIG;
                if (j0 + c0 > r1) s[nt][2] = NEG_BIG;
                if (j0 + c1 > r1) s[nt][3] = NEG_BIG;
            }
            mt0 = fmaxf(mt0, fmaxf(s[nt][0], s[nt][1]));
            mt1 = fmaxf(mt1, fmaxf(s[nt][2], s[nt][3]));
        }
        mt0 = fmaxf(mt0, __shfl_xor_sync(0xffffffffu, mt0, 1));
        mt0 = fmaxf(mt0, __shfl_xor_sync(0xffffffffu, mt0, 2));
        mt1 = fmaxf(mt1, __shfl_xor_sync(0xffffffffu, mt1, 1));
        mt1 = fmaxf(mt1, __shfl_xor_sync(0xffffffffu, mt1, 2));

        float mn0 = fmaxf(m0, mt0), mn1 = fmaxf(m1, mt1);
        float al0 = fex2(m0 - mn0), al1 = fex2(m1 - mn1);
        float ps0 = 0.f, ps1 = 0.f;
#pragma unroll
        for (int nt = 0; nt < 8; nt++) {
            s[nt][0] = fex2(s[nt][0] - mn0);
            s[nt][1] = fex2(s[nt][1] - mn0);
            s[nt][2] = fex2(s[nt][2] - mn1);
            s[nt][3] = fex2(s[nt][3] - mn1);
            ps0 += s[nt][0] + s[nt][1];
            ps1 += s[nt][2] + s[nt][3];
        }
        ps0 += __shfl_xor_sync(0xffffffffu, ps0, 1);
        ps0 += __shfl_xor_sync(0xffffffffu, ps0, 2);
        ps1 += __shfl_xor_sync(0xffffffffu, ps1, 1);
        ps1 += __shfl_xor_sync(0xffffffffu, ps1, 2);
        l0 = l0 * al0 + ps0;
        l1 = l1 * al1 + ps1;
        m0 = mn0; m1 = mn1;
#pragma unroll
        for (int nt = 0; nt < 8; nt++) {
            o[nt][0] *= al0; o[nt][1] *= al0;
            o[nt][2] *= al1; o[nt][3] *= al1;
        }

        __syncthreads();
        const int pr0 = (wid << 4) + grp, pr1 = pr0 + 8;
#pragma unroll
        for (int nt = 0; nt < 8; nt++) {
            int c0 = (nt << 3) + (tg << 1);
            *(float2*)&KP[pr0][c0] = make_float2(
                __uint_as_float(tf32r(s[nt][0])), __uint_as_float(tf32r(s[nt][1])));
            *(float2*)&KP[pr1][c0] = make_float2(
                __uint_as_float(tf32r(s[nt][2])), __uint_as_float(tf32r(s[nt][3])));
        }
        __syncwarp();

#pragma unroll
        for (int kt = 0; kt < 8; kt++) {
            uint32_t pa[4];
            pa[0] = __float_as_uint(KP[pr0][(kt << 3) + tg]);
            pa[1] = __float_as_uint(KP[pr1][(kt << 3) + tg]);
            pa[2] = __float_as_uint(KP[pr0][(kt << 3) + tg + 4]);
            pa[3] = __float_as_uint(KP[pr1][(kt << 3) + tg + 4]);
#pragma unroll
            for (int nt = 0; nt < 8; nt++) {
                uint32_t b0 = __float_as_uint(Vs[(kt << 3) + tg][(nt << 3) + grp]);
                uint32_t b1 = __float_as_uint(Vs[(kt << 3) + tg + 4][(nt << 3) + grp]);
                mma_tf32(o[nt], pa, b0, b1);
            }
        }
    }

    const float iv0 = 1.f / l0, iv1 = 1.f / l1;
#pragma unroll
    for (int nt = 0; nt < 8; nt++) {
        int col = h * 64 + (nt << 3) + (tg << 1);
        *(float2*)&y[(size_t)r0 * C_DIM + col] =
            make_float2(o[nt][0] * iv0, o[nt][1] * iv0);
        *(float2*)&y[(size_t)r1 * C_DIM + col] =
            make_float2(o[nt][2] * iv1, o[nt][3] * iv1);
    }
}

// ---------------------------------------------------------------------------
// kernel_launch — ncu profiles MY launch index 3 (normrope this round)
// ---------------------------------------------------------------------------
extern "C" void kernel_launch(void* const* d_in, const int* in_sizes, int n_in,
                              void* d_out, int out_size) {
    const float* x  = (const float*)d_in[0];
    const float* Wq = (const float*)d_in[1];
    const float* Wk = (const float*)d_in[2];
    const float* Wv = (const float*)d_in[3];
    const float* Wo = (const float*)d_in[4];
    const float* qw = (const float*)d_in[5];
    const float* kw = (const float*)d_in[6];
    const float* fg = (const float*)d_in[7];
    const float* fb = (const float*)d_in[8];
    const float* wl = (const float*)d_in[9];
    float* out = (float*)d_out;

    float *qp, *kp, *vp, *yp, *lfp, *cp;
    cudaGetSymbolAddress((void**)&qp, g_q);
    cudaGetSymbolAddress((void**)&kp, g_k);
    cudaGetSymbolAddress((void**)&vp, g_v);
    cudaGetSymbolAddress((void**)&yp, g_y);
    cudaGetSymbolAddress((void**)&lfp, g_logf);
    cudaGetSymbolAddress((void**)&cp, g_c);

    // 0: gate, 1: scan
    gate_kernel<<<T_LEN / 8, 256>>>(x, wl, fg, fb, lfp);
    scan_kernel<<<H_NUM, 32>>>(lfp, cp);

    // 2: fused Q/K/V projection — 24 n-tiles x 16 m-tiles = 384 blocks
    gemm_tf32_kernel<<<dim3(24, T_LEN / 128), 256>>>(
        x, Wq, qp, Wk, kp, Wv, vp, C_DIM, 1);

    // 3: RMSNorm + RoPE (profiled this round)
    normrope_kernel<<<T_LEN, 256>>>(qp, kp, qw, kw);

    // 4: flash attention
    attn_tf32_kernel<<<dim3(T_LEN / 64, H_NUM), 128>>>(qp, kp, vp, cp, yp);

    // 5: output projection — 16x16 = 256 blocks
    gemm_tf32_kernel<<<dim3(16, T_LEN / 128), 256>>>(
        yp, Wo, out, Wo, out, Wo, out, C_DIM, 0);
}